// round 15
// baseline (speedup 1.0000x reference)
#include <cuda_runtime.h>
#include <math.h>

#define NN   1024
#define EIN  4096
#define ET   5120
#define NTE  5119
#define C1   16
#define C2   7
#define INC  1433
#define WPB  8                        // warps per TE block
#define BPC  ((NTE + WPB - 1) / WPB)  // 640 blocks per channel
#define PAD  128
#define CSTR (NTE + 2 * PAD)          // per-channel stride incl. pads

// ---------------- device scratch ----------------
__device__ float  g_dig[NTE + 1];
__device__ float  g_h1[NN * C1];
__device__ float  g_h2[NN * C2];
__device__ float4 g_s4[C1 * CSTR];
__device__ float  g_tesum1[C1];
__device__ float  g_tesum2[C2];
__device__ float  g_agg1[NN * C1];
__device__ float  g_agg2[NN * C2];
__device__ float  g_cnt[NN];

__device__ __forceinline__ float f_inf() { return __int_as_float(0x7f800000); }

// ---------------- layer-1 GEMM + folded init ----------------
__global__ void k_gemm1(const float* __restrict__ x,
                        const float* __restrict__ W1,
                        const float* __restrict__ b1) {
    int gt = blockIdx.x * 512 + threadIdx.x;
    if (gt < NN * C1) g_agg1[gt] = 0.f;
    if (gt < NN * C2) g_agg2[gt] = 0.f;
    if (gt < NN)      g_cnt[gt]  = 0.f;
    if (gt < C1)      g_tesum1[gt] = 0.f;
    if (gt < C2)      g_tesum2[gt] = 0.f;
    if (gt >= 1 && gt <= NTE) {
        double xx = (double)gt, r = 0.0;
        while (xx < 8.0) { r -= 1.0 / xx; xx += 1.0; }
        double ix = 1.0 / xx, ix2 = ix * ix;
        r += log(xx) - 0.5 * ix
           - ix2 * ((1.0/12.0) - ix2 * ((1.0/120.0) - ix2 * (1.0/252.0)));
        g_dig[gt] = (float)r;
    }
    if (gt == 0) g_dig[0] = 0.f;

    int v    = blockIdx.x;
    int warp = threadIdx.x >> 5;
    int lane = threadIdx.x & 31;
    const float* xr = x  + (size_t)v    * INC;
    const float* wr = W1 + (size_t)warp * INC;
    float s = 0.f;
    for (int k = lane; k < INC; k += 32) s += xr[k] * wr[k];
    #pragma unroll
    for (int o = 16; o; o >>= 1) s += __shfl_xor_sync(0xffffffffu, s, o);
    if (lane == 0) g_h1[v * C1 + warp] = s + b1[warp];
}

// ------- shared sort machinery: bitonic over 1024 node values + histogram scatter ----
__device__ __forceinline__ void sort_scatter(const int* __restrict__ ei, int c,
                                             const float* hvals, int strideC,
                                             unsigned long long* sk, int* rankof,
                                             int* cnt, int* offs) {
    const int tid = threadIdx.x;
    const unsigned FULL = 0xffffffffu;

    unsigned long long kv;
    {
        unsigned u = __float_as_uint(hvals[tid * strideC]);
        u = (u & 0x80000000u) ? ~u : (u | 0x80000000u);
        kv = ((unsigned long long)u << 32) | (unsigned)tid;
        cnt[tid] = 0;
    }

    for (int k = 2; k <= 1024; k <<= 1) {
        for (int j = k >> 1; j > 0; j >>= 1) {
            bool up = ((tid & k) == 0);
            unsigned long long other;
            if (j >= 32) {
                __syncthreads();
                sk[tid] = kv;
                __syncthreads();
                other = sk[tid ^ j];
            } else {
                other = __shfl_xor_sync(FULL, kv, j);
            }
            bool keepmin = (((tid & j) == 0) == up);
            bool swap = keepmin ? (other < kv) : (other > kv);
            if (swap) kv = other;
        }
    }
    __syncthreads();
    rankof[(int)(kv & 1023u)] = tid;
    __syncthreads();

    for (int t = tid; t < NTE; t += 1024) {
        int s0 = (t < EIN) ? ei[t] : (t - EIN);
        atomicAdd(&cnt[rankof[s0]], 1);
    }
    __syncthreads();

    int orig = cnt[tid];
    for (int off = 1; off < 1024; off <<= 1) {
        int add = (tid >= off) ? cnt[tid - off] : 0;
        __syncthreads();
        cnt[tid] += add;
        __syncthreads();
    }
    offs[tid] = cnt[tid] - orig;
    __syncthreads();

    float4* S = g_s4 + (size_t)c * CSTR + PAD;
    // sentinel pads: left y=-inf (dy=+inf), right y=+inf (dy=+inf)
    if (tid < PAD) {
        S[-1 - tid]  = make_float4(0.f, -f_inf(), 0.f, 0.f);
        S[NTE + tid] = make_float4(0.f,  f_inf(), 0.f, 0.f);
    }
    for (int t = tid; t < NTE; t += 1024) {
        int s0 = (t < EIN) ? ei[t]       : (t - EIN);
        int d0 = (t < EIN) ? ei[EIN + t] : (t - EIN);
        int t1 = t + 1;
        int s1 = (t1 < EIN) ? ei[t1]     : (t1 - EIN);
        int slot = atomicAdd(&offs[rankof[s0]], 1);
        S[slot] = make_float4(hvals[d0 * strideC], hvals[s0 * strideC], hvals[s1 * strideC], 0.f);
    }
}

// ---------------- layer-1 sort ----------------
__global__ __launch_bounds__(1024) void k_sort1(const int* __restrict__ ei) {
    __shared__ unsigned long long sk[1024];
    __shared__ int rankof[1024];
    __shared__ int cnt[1024];
    __shared__ int offs[1024];
    int c = blockIdx.x;
    sort_scatter(ei, c, g_h1 + c, C1, sk, rankof, cnt, offs);
}

// ---------------- layer-2: fused gemm2 + sort ----------------
__global__ __launch_bounds__(1024) void k_sort2(const int* __restrict__ ei,
                                                const float* __restrict__ W2,
                                                const float* __restrict__ b2) {
    __shared__ unsigned long long sk[1024];
    __shared__ int rankof[1024];
    __shared__ int cnt[1024];
    __shared__ int offs[1024];
    __shared__ float h2c[1024];
    const int c   = blockIdx.x;
    const int tid = threadIdx.x;

    {
        float inv = 1.0f / fmaxf(g_cnt[tid], 1.0f);
        float s = b2[c];
        #pragma unroll
        for (int cc = 0; cc < C1; cc++)
            s += W2[c * C1 + cc] * fmaxf(g_agg1[tid * C1 + cc] * inv, 0.0f);
        h2c[tid] = s;
        g_h2[tid * C2 + c] = s;
    }
    __syncthreads();

    sort_scatter(ei, c, h2c, 1, sk, rankof, cnt, offs);
}

// ---------------- KSG TE: one warp per point, sentinel-padded scans ----------------
__global__ __launch_bounds__(32 * WPB) void k_te(int layer) {
    float* tesum = (layer == 1) ? g_tesum1 : g_tesum2;
    const int c  = blockIdx.x / BPC;
    const int bi = blockIdx.x - c * BPC;
    const int wid  = threadIdx.x >> 5;
    const int lane = threadIdx.x & 31;
    const int p    = bi * WPB + wid;
    const unsigned FULL = 0xffffffffu;

    const float4* __restrict__ S = g_s4 + (size_t)c * CSTR + PAD;

    if (p < NTE) {
        float4 pi = S[p];
        float xi = pi.x, yi = pi.y, zi = pi.z;

        // ==== phase A: eps via alternating L/R 64-chunks (no bounds checks) ====
        float eps = f_inf();
        int jbL = p - 1, jbR = p + 1;
        bool actL = true, actR = true;
        while (actL || actR) {
            if (actL) {
                float4 q0 = S[jbL - lane];
                float4 q1 = S[jbL - 32 - lane];
                float dy1 = yi - q1.y;
                float m0 = fmaxf(yi - q0.y, fmaxf(fabsf(xi - q0.x), fabsf(zi - q0.z)));
                float m1 = fmaxf(dy1,       fmaxf(fabsf(xi - q1.x), fabsf(zi - q1.z)));
                float m  = fminf(m0, m1);
                unsigned mu = __reduce_min_sync(FULL, __float_as_uint(m));  // m >= 0
                eps = fminf(eps, __uint_as_float(mu));
                float dyf = __shfl_sync(FULL, dy1, 31);   // farthest scanned dy (pad -> +inf)
                jbL -= 64;
                actL = (dyf < eps);
            }
            if (actR) {
                float4 q0 = S[jbR + lane];
                float4 q1 = S[jbR + 32 + lane];
                float dy1 = q1.y - yi;
                float m0 = fmaxf(q0.y - yi, fmaxf(fabsf(xi - q0.x), fabsf(zi - q0.z)));
                float m1 = fmaxf(dy1,       fmaxf(fabsf(xi - q1.x), fabsf(zi - q1.z)));
                float m  = fminf(m0, m1);
                unsigned mu = __reduce_min_sync(FULL, __float_as_uint(m));
                eps = fminf(eps, __uint_as_float(mu));
                float dyf = __shfl_sync(FULL, dy1, 31);
                jbR += 64;
                actR = (dyf < eps);
            }
        }

        // ==== phase B: per-lane counts, 128 points per iteration (PAD=128 covers) ====
        int cy = (lane == 0) ? 1 : 0;
        int cxy = cy, cyz = cy;
        for (int jb = p - 1; ; jb -= 128) {
            float4 q0 = S[jb - lane];
            float4 q1 = S[jb - 32 - lane];
            float4 q2 = S[jb - 64 - lane];
            float4 q3 = S[jb - 96 - lane];
            bool in0 = (yi - q0.y) < eps;      // pad: dy=+inf -> false
            bool in1 = (yi - q1.y) < eps;
            bool in2 = (yi - q2.y) < eps;
            bool in3 = (yi - q3.y) < eps;
            cy  += (in0 + in1) + (in2 + in3);
            cxy += ((in0 && (fabsf(xi - q0.x) < eps)) + (in1 && (fabsf(xi - q1.x) < eps)))
                 + ((in2 && (fabsf(xi - q2.x) < eps)) + (in3 && (fabsf(xi - q3.x) < eps)));
            cyz += ((in0 && (fabsf(zi - q0.z) < eps)) + (in1 && (fabsf(zi - q1.z) < eps)))
                 + ((in2 && (fabsf(zi - q2.z) < eps)) + (in3 && (fabsf(zi - q3.z) < eps)));
            int cont = __shfl_sync(FULL, (int)in3, 31);   // deepest of the 128
            if (!cont) break;
        }
        for (int jb = p + 1; ; jb += 128) {
            float4 q0 = S[jb + lane];
            float4 q1 = S[jb + 32 + lane];
            float4 q2 = S[jb + 64 + lane];
            float4 q3 = S[jb + 96 + lane];
            bool in0 = (q0.y - yi) < eps;
            bool in1 = (q1.y - yi) < eps;
            bool in2 = (q2.y - yi) < eps;
            bool in3 = (q3.y - yi) < eps;
            cy  += (in0 + in1) + (in2 + in3);
            cxy += ((in0 && (fabsf(xi - q0.x) < eps)) + (in1 && (fabsf(xi - q1.x) < eps)))
                 + ((in2 && (fabsf(xi - q2.x) < eps)) + (in3 && (fabsf(xi - q3.x) < eps)));
            cyz += ((in0 && (fabsf(zi - q0.z) < eps)) + (in1 && (fabsf(zi - q1.z) < eps)))
                 + ((in2 && (fabsf(zi - q2.z) < eps)) + (in3 && (fabsf(zi - q3.z) < eps)));
            int cont = __shfl_sync(FULL, (int)in3, 31);
            if (!cont) break;
        }
        cy  = __reduce_add_sync(FULL, cy);
        cxy = __reduce_add_sync(FULL, cxy);
        cyz = __reduce_add_sync(FULL, cyz);
        float val = g_dig[cy] - g_dig[cxy] - g_dig[cyz];    // warp-uniform
        if (lane == 0) atomicAdd(&tesum[c], val);
    }
}

// ---------------- aggregation ----------------
__global__ void k_agg(const int* __restrict__ ei, int layer, int C) {
    int idx = blockIdx.x * blockDim.x + threadIdx.x;
    if (idx >= ET * C) return;
    const float* h     = (layer == 1) ? g_h1 : g_h2;
    const float* tesum = (layer == 1) ? g_tesum1 : g_tesum2;
    float*       agg   = (layer == 1) ? g_agg1 : g_agg2;
    int e = idx / C, c = idx - e * C;
    int s = (e < EIN) ? ei[e]       : (e - EIN);
    int d = (e < EIN) ? ei[EIN + e] : (e - EIN);
    float tes = -0.57721566490153286f + tesum[c] * (1.0f / (float)NTE);
    if (layer == 2) tes *= 0.5f;
    float m = 1.0f / (1.0f + expf(-tes * h[s * C + c]));
    atomicAdd(&agg[d * C + c], m);
    if (layer == 1 && c == 0) atomicAdd(&g_cnt[d], 1.0f);
}

// ---------------- final: mean + log_softmax ----------------
__global__ void k_final(float* __restrict__ out) {
    int v = blockIdx.x * blockDim.x + threadIdx.x;
    if (v >= NN) return;
    float inv = 1.0f / fmaxf(g_cnt[v], 1.0f);
    float val[C2], mx = -f_inf();
    #pragma unroll
    for (int o = 0; o < C2; o++) {
        val[o] = g_agg2[v * C2 + o] * inv;
        mx = fmaxf(mx, val[o]);
    }
    float s = 0.f;
    #pragma unroll
    for (int o = 0; o < C2; o++) s += expf(val[o] - mx);
    float ls = mx + logf(s);
    #pragma unroll
    for (int o = 0; o < C2; o++) out[v * C2 + o] = val[o] - ls;
}

// ---------------- launch (inputs identified by element count) ----------------
extern "C" void kernel_launch(void* const* d_in, const int* in_sizes, int n_in,
                              void* d_out, int out_size) {
    const float* x  = nullptr;
    const int*   ei = nullptr;
    const float* W1 = nullptr;
    const float* b1 = nullptr;
    const float* W2 = nullptr;
    const float* b2 = nullptr;
    for (int k = 0; k < n_in; k++) {
        switch (in_sizes[k]) {
            case NN * INC:  x  = (const float*)d_in[k]; break;
            case 2 * EIN:   ei = (const int*)  d_in[k]; break;
            case C1 * INC:  W1 = (const float*)d_in[k]; break;
            case C1:        b1 = (const float*)d_in[k]; break;
            case C2 * C1:   W2 = (const float*)d_in[k]; break;
            case C2:        b2 = (const float*)d_in[k]; break;
            default: break;
        }
    }
    float* out = (float*)d_out;

    // layer 1 (init folded into gemm1)
    k_gemm1  <<<NN, 512>>>(x, W1, b1);
    k_sort1  <<<C1, 1024>>>(ei);
    k_te     <<<C1 * BPC, 32 * WPB>>>(1);
    k_agg    <<<(ET * C1 + 255) / 256, 256>>>(ei, 1, C1);

    // layer 2 (gemm2 fused into sort2)
    k_sort2  <<<C2, 1024>>>(ei, W2, b2);
    k_te     <<<C2 * BPC, 32 * WPB>>>(2);
    k_agg    <<<(ET * C2 + 255) / 256, 256>>>(ei, 2, C2);

    k_final  <<<(NN + 255) / 256, 256>>>(out);
}

// round 16
// speedup vs baseline: 1.8663x; 1.8663x over previous
#include <cuda_runtime.h>
#include <math.h>

#define NN   1024
#define EIN  4096
#define ET   5120
#define NTE  5119
#define C1   16
#define C2   7
#define INC  1433
#define WPB  8                        // warps per TE block
#define BPC  ((NTE + WPB - 1) / WPB)  // 640 blocks per channel
#define PAD  128
#define CSTR (NTE + 2 * PAD)          // per-channel stride incl. pads

// ---------------- device scratch ----------------
__device__ float  g_dig[NTE + 1];
__device__ float  g_h1[NN * C1];
__device__ float  g_h2[NN * C2];
__device__ float4 g_s4[C1 * CSTR];
__device__ float  g_tesum1[C1];
__device__ float  g_tesum2[C2];
__device__ float  g_agg1[NN * C1];
__device__ float  g_agg2[NN * C2];
__device__ float  g_cnt[NN];

__device__ __forceinline__ float f_inf() { return __int_as_float(0x7f800000); }

// ---------------- layer-1 GEMM + folded init ----------------
__global__ void k_gemm1(const float* __restrict__ x,
                        const float* __restrict__ W1,
                        const float* __restrict__ b1) {
    int gt = blockIdx.x * 512 + threadIdx.x;
    if (gt < NN * C1) g_agg1[gt] = 0.f;
    if (gt < NN * C2) g_agg2[gt] = 0.f;
    if (gt < NN)      g_cnt[gt]  = 0.f;
    if (gt < C1)      g_tesum1[gt] = 0.f;
    if (gt < C2)      g_tesum2[gt] = 0.f;
    if (gt >= 1 && gt <= NTE) {
        double xx = (double)gt, r = 0.0;
        while (xx < 8.0) { r -= 1.0 / xx; xx += 1.0; }
        double ix = 1.0 / xx, ix2 = ix * ix;
        r += log(xx) - 0.5 * ix
           - ix2 * ((1.0/12.0) - ix2 * ((1.0/120.0) - ix2 * (1.0/252.0)));
        g_dig[gt] = (float)r;
    }
    if (gt == 0) g_dig[0] = 0.f;

    int v    = blockIdx.x;
    int warp = threadIdx.x >> 5;
    int lane = threadIdx.x & 31;
    const float* xr = x  + (size_t)v    * INC;
    const float* wr = W1 + (size_t)warp * INC;
    float s = 0.f;
    for (int k = lane; k < INC; k += 32) s += xr[k] * wr[k];
    #pragma unroll
    for (int o = 16; o; o >>= 1) s += __shfl_xor_sync(0xffffffffu, s, o);
    if (lane == 0) g_h1[v * C1 + warp] = s + b1[warp];
}

// ------- shared sort machinery: bitonic over 1024 node values + histogram scatter ----
__device__ __forceinline__ void sort_scatter(const int* __restrict__ ei, int c,
                                             const float* hvals, int strideC,
                                             unsigned long long* sk, int* rankof,
                                             int* cnt, int* offs) {
    const int tid = threadIdx.x;
    const unsigned FULL = 0xffffffffu;

    unsigned long long kv;
    {
        unsigned u = __float_as_uint(hvals[tid * strideC]);
        u = (u & 0x80000000u) ? ~u : (u | 0x80000000u);
        kv = ((unsigned long long)u << 32) | (unsigned)tid;
        cnt[tid] = 0;
    }

    for (int k = 2; k <= 1024; k <<= 1) {
        for (int j = k >> 1; j > 0; j >>= 1) {
            bool up = ((tid & k) == 0);
            unsigned long long other;
            if (j >= 32) {
                __syncthreads();
                sk[tid] = kv;
                __syncthreads();
                other = sk[tid ^ j];
            } else {
                other = __shfl_xor_sync(FULL, kv, j);
            }
            bool keepmin = (((tid & j) == 0) == up);
            bool swap = keepmin ? (other < kv) : (other > kv);
            if (swap) kv = other;
        }
    }
    __syncthreads();
    rankof[(int)(kv & 1023u)] = tid;
    __syncthreads();

    for (int t = tid; t < NTE; t += 1024) {
        int s0 = (t < EIN) ? ei[t] : (t - EIN);
        atomicAdd(&cnt[rankof[s0]], 1);
    }
    __syncthreads();

    int orig = cnt[tid];
    for (int off = 1; off < 1024; off <<= 1) {
        int add = (tid >= off) ? cnt[tid - off] : 0;
        __syncthreads();
        cnt[tid] += add;
        __syncthreads();
    }
    offs[tid] = cnt[tid] - orig;
    __syncthreads();

    float4* S = g_s4 + (size_t)c * CSTR + PAD;
    // sentinel pads: left y=-inf (dy=+inf), right y=+inf (dy=+inf)
    if (tid < PAD) {
        S[-1 - tid]  = make_float4(0.f, -f_inf(), 0.f, 0.f);
        S[NTE + tid] = make_float4(0.f,  f_inf(), 0.f, 0.f);
    }
    for (int t = tid; t < NTE; t += 1024) {
        int s0 = (t < EIN) ? ei[t]       : (t - EIN);
        int d0 = (t < EIN) ? ei[EIN + t] : (t - EIN);
        int t1 = t + 1;
        int s1 = (t1 < EIN) ? ei[t1]     : (t1 - EIN);
        int slot = atomicAdd(&offs[rankof[s0]], 1);
        S[slot] = make_float4(hvals[d0 * strideC], hvals[s0 * strideC], hvals[s1 * strideC], 0.f);
    }
}

// ---------------- layer-1 sort ----------------
__global__ __launch_bounds__(1024) void k_sort1(const int* __restrict__ ei) {
    __shared__ unsigned long long sk[1024];
    __shared__ int rankof[1024];
    __shared__ int cnt[1024];
    __shared__ int offs[1024];
    int c = blockIdx.x;
    sort_scatter(ei, c, g_h1 + c, C1, sk, rankof, cnt, offs);
}

// ---------------- layer-2: fused gemm2 + sort ----------------
__global__ __launch_bounds__(1024) void k_sort2(const int* __restrict__ ei,
                                                const float* __restrict__ W2,
                                                const float* __restrict__ b2) {
    __shared__ unsigned long long sk[1024];
    __shared__ int rankof[1024];
    __shared__ int cnt[1024];
    __shared__ int offs[1024];
    __shared__ float h2c[1024];
    const int c   = blockIdx.x;
    const int tid = threadIdx.x;

    {
        float inv = 1.0f / fmaxf(g_cnt[tid], 1.0f);
        float s = b2[c];
        #pragma unroll
        for (int cc = 0; cc < C1; cc++)
            s += W2[c * C1 + cc] * fmaxf(g_agg1[tid * C1 + cc] * inv, 0.0f);
        h2c[tid] = s;
        g_h2[tid * C2 + c] = s;
    }
    __syncthreads();

    sort_scatter(ei, c, h2c, 1, sk, rankof, cnt, offs);
}

// ---------------- KSG TE: one warp per point, sentinel-padded scans ----------------
__global__ __launch_bounds__(32 * WPB) void k_te(int layer) {
    float* tesum = (layer == 1) ? g_tesum1 : g_tesum2;
    const int c  = blockIdx.x / BPC;
    const int bi = blockIdx.x - c * BPC;
    const int wid  = threadIdx.x >> 5;
    const int lane = threadIdx.x & 31;
    const int p    = bi * WPB + wid;
    const unsigned FULL = 0xffffffffu;

    const float4* __restrict__ S = g_s4 + (size_t)c * CSTR + PAD;

    float val = 0.f;
    if (p < NTE) {
        float4 pi = S[p];
        float xi = pi.x, yi = pi.y, zi = pi.z;

        // ==== phase A: eps via alternating L/R 64-chunks (no bounds checks) ====
        float eps = f_inf();
        int jbL = p - 1, jbR = p + 1;
        bool actL = true, actR = true;
        while (actL || actR) {
            if (actL) {
                float4 q0 = S[jbL - lane];
                float4 q1 = S[jbL - 32 - lane];
                float dy1 = yi - q1.y;
                float m0 = fmaxf(yi - q0.y, fmaxf(fabsf(xi - q0.x), fabsf(zi - q0.z)));
                float m1 = fmaxf(dy1,       fmaxf(fabsf(xi - q1.x), fabsf(zi - q1.z)));
                float m  = fminf(m0, m1);
                unsigned mu = __reduce_min_sync(FULL, __float_as_uint(m));  // m >= 0
                eps = fminf(eps, __uint_as_float(mu));
                float dyf = __shfl_sync(FULL, dy1, 31);   // farthest scanned dy (pad -> +inf)
                jbL -= 64;
                actL = (dyf < eps);
            }
            if (actR) {
                float4 q0 = S[jbR + lane];
                float4 q1 = S[jbR + 32 + lane];
                float dy1 = q1.y - yi;
                float m0 = fmaxf(q0.y - yi, fmaxf(fabsf(xi - q0.x), fabsf(zi - q0.z)));
                float m1 = fmaxf(dy1,       fmaxf(fabsf(xi - q1.x), fabsf(zi - q1.z)));
                float m  = fminf(m0, m1);
                unsigned mu = __reduce_min_sync(FULL, __float_as_uint(m));
                eps = fminf(eps, __uint_as_float(mu));
                float dyf = __shfl_sync(FULL, dy1, 31);
                jbR += 64;
                actR = (dyf < eps);
            }
        }

        // ==== phase B: per-lane counts, 128 points per iteration (PAD=128 covers) ====
        int cy = (lane == 0) ? 1 : 0;
        int cxy = cy, cyz = cy;
        for (int jb = p - 1; ; jb -= 128) {
            float4 q0 = S[jb - lane];
            float4 q1 = S[jb - 32 - lane];
            float4 q2 = S[jb - 64 - lane];
            float4 q3 = S[jb - 96 - lane];
            bool in0 = (yi - q0.y) < eps;      // pad: dy=+inf -> false
            bool in1 = (yi - q1.y) < eps;
            bool in2 = (yi - q2.y) < eps;
            bool in3 = (yi - q3.y) < eps;
            cy  += (in0 + in1) + (in2 + in3);
            cxy += ((in0 && (fabsf(xi - q0.x) < eps)) + (in1 && (fabsf(xi - q1.x) < eps)))
                 + ((in2 && (fabsf(xi - q2.x) < eps)) + (in3 && (fabsf(xi - q3.x) < eps)));
            cyz += ((in0 && (fabsf(zi - q0.z) < eps)) + (in1 && (fabsf(zi - q1.z) < eps)))
                 + ((in2 && (fabsf(zi - q2.z) < eps)) + (in3 && (fabsf(zi - q3.z) < eps)));
            int cont = __shfl_sync(FULL, (int)in3, 31);   // deepest of the 128
            if (!cont) break;
        }
        for (int jb = p + 1; ; jb += 128) {
            float4 q0 = S[jb + lane];
            float4 q1 = S[jb + 32 + lane];
            float4 q2 = S[jb + 64 + lane];
            float4 q3 = S[jb + 96 + lane];
            bool in0 = (q0.y - yi) < eps;
            bool in1 = (q1.y - yi) < eps;
            bool in2 = (q2.y - yi) < eps;
            bool in3 = (q3.y - yi) < eps;
            cy  += (in0 + in1) + (in2 + in3);
            cxy += ((in0 && (fabsf(xi - q0.x) < eps)) + (in1 && (fabsf(xi - q1.x) < eps)))
                 + ((in2 && (fabsf(xi - q2.x) < eps)) + (in3 && (fabsf(xi - q3.x) < eps)));
            cyz += ((in0 && (fabsf(zi - q0.z) < eps)) + (in1 && (fabsf(zi - q1.z) < eps)))
                 + ((in2 && (fabsf(zi - q2.z) < eps)) + (in3 && (fabsf(zi - q3.z) < eps)));
            int cont = __shfl_sync(FULL, (int)in3, 31);
            if (!cont) break;
        }
        cy  = __reduce_add_sync(FULL, cy);
        cxy = __reduce_add_sync(FULL, cxy);
        cyz = __reduce_add_sync(FULL, cyz);
        val = g_dig[cy] - g_dig[cxy] - g_dig[cyz];          // warp-uniform
    }

    // block reduction -> ONE atomic per block (R14 scheme; avoids same-addr atomic chains)
    __shared__ float red[WPB];
    if (lane == 0) red[wid] = val;
    __syncthreads();
    if (threadIdx.x == 0) {
        float s = 0.f;
        #pragma unroll
        for (int q = 0; q < WPB; q++) s += red[q];
        atomicAdd(&tesum[c], s);
    }
}

// ---------------- aggregation ----------------
__global__ void k_agg(const int* __restrict__ ei, int layer, int C) {
    int idx = blockIdx.x * blockDim.x + threadIdx.x;
    if (idx >= ET * C) return;
    const float* h     = (layer == 1) ? g_h1 : g_h2;
    const float* tesum = (layer == 1) ? g_tesum1 : g_tesum2;
    float*       agg   = (layer == 1) ? g_agg1 : g_agg2;
    int e = idx / C, c = idx - e * C;
    int s = (e < EIN) ? ei[e]       : (e - EIN);
    int d = (e < EIN) ? ei[EIN + e] : (e - EIN);
    float tes = -0.57721566490153286f + tesum[c] * (1.0f / (float)NTE);
    if (layer == 2) tes *= 0.5f;
    float m = 1.0f / (1.0f + expf(-tes * h[s * C + c]));
    atomicAdd(&agg[d * C + c], m);
    if (layer == 1 && c == 0) atomicAdd(&g_cnt[d], 1.0f);
}

// ---------------- final: mean + log_softmax ----------------
__global__ void k_final(float* __restrict__ out) {
    int v = blockIdx.x * blockDim.x + threadIdx.x;
    if (v >= NN) return;
    float inv = 1.0f / fmaxf(g_cnt[v], 1.0f);
    float val[C2], mx = -f_inf();
    #pragma unroll
    for (int o = 0; o < C2; o++) {
        val[o] = g_agg2[v * C2 + o] * inv;
        mx = fmaxf(mx, val[o]);
    }
    float s = 0.f;
    #pragma unroll
    for (int o = 0; o < C2; o++) s += expf(val[o] - mx);
    float ls = mx + logf(s);
    #pragma unroll
    for (int o = 0; o < C2; o++) out[v * C2 + o] = val[o] - ls;
}

// ---------------- launch (inputs identified by element count) ----------------
extern "C" void kernel_launch(void* const* d_in, const int* in_sizes, int n_in,
                              void* d_out, int out_size) {
    const float* x  = nullptr;
    const int*   ei = nullptr;
    const float* W1 = nullptr;
    const float* b1 = nullptr;
    const float* W2 = nullptr;
    const float* b2 = nullptr;
    for (int k = 0; k < n_in; k++) {
        switch (in_sizes[k]) {
            case NN * INC:  x  = (const float*)d_in[k]; break;
            case 2 * EIN:   ei = (const int*)  d_in[k]; break;
            case C1 * INC:  W1 = (const float*)d_in[k]; break;
            case C1:        b1 = (const float*)d_in[k]; break;
            case C2 * C1:   W2 = (const float*)d_in[k]; break;
            case C2:        b2 = (const float*)d_in[k]; break;
            default: break;
        }
    }
    float* out = (float*)d_out;

    // layer 1 (init folded into gemm1)
    k_gemm1  <<<NN, 512>>>(x, W1, b1);
    k_sort1  <<<C1, 1024>>>(ei);
    k_te     <<<C1 * BPC, 32 * WPB>>>(1);
    k_agg    <<<(ET * C1 + 255) / 256, 256>>>(ei, 1, C1);

    // layer 2 (gemm2 fused into sort2)
    k_sort2  <<<C2, 1024>>>(ei, W2, b2);
    k_te     <<<C2 * BPC, 32 * WPB>>>(2);
    k_agg    <<<(ET * C2 + 255) / 256, 256>>>(ei, 2, C2);

    k_final  <<<(NN + 255) / 256, 256>>>(out);
}